// round 9
// baseline (speedup 1.0000x reference)
#include <cuda_runtime.h>
#include <cuda_bf16.h>
#include <cstdint>

#define DIM   64
#define MM_   64
#define NB    2048
#define LL    2
#define NREL  32
#define PAIRS (2 * NB)
#define GRIDP 592          // 148 SM * 4 blocks, all resident

// Scratch (no dynamic allocation allowed)
__device__ __nv_bfloat16 g_waggTb[3 * DIM * DIM];  // [k][j], bf16 (idempotent writes)
__device__ float g_side[2][NB][DIM];
__device__ int   g_ctr;          // work-stealing counter (self-cleaning)
__device__ int   g_exit;         // exit counter (self-cleaning)

__device__ __forceinline__ float sigmoidf_(float x) {
    return 1.f / (1.f + __expf(-x));
}
__device__ __forceinline__ uint32_t smem_u32(const void* p) {
    return (uint32_t)__cvta_generic_to_shared(p);
}
__device__ __forceinline__ void ldm_x4(uint32_t& r0, uint32_t& r1, uint32_t& r2, uint32_t& r3, uint32_t a) {
    asm volatile("ldmatrix.sync.aligned.m8n8.x4.shared.b16 {%0,%1,%2,%3},[%4];\n"
                 : "=r"(r0), "=r"(r1), "=r"(r2), "=r"(r3) : "r"(a));
}
__device__ __forceinline__ void mma_bf16(float* d, uint32_t a0, uint32_t a1, uint32_t a2, uint32_t a3,
                                         uint32_t b0, uint32_t b1) {
    asm volatile("mma.sync.aligned.m16n8k16.row.col.f32.bf16.bf16.f32 "
                 "{%0,%1,%2,%3},{%4,%5,%6,%7},{%8,%9},{%0,%1,%2,%3};\n"
                 : "+f"(d[0]), "+f"(d[1]), "+f"(d[2]), "+f"(d[3])
                 : "r"(a0), "r"(a1), "r"(a2), "r"(a3), "r"(b0), "r"(b1));
}

// ---------------------------------------------------------------------------
// Persistent attention + aggregation (staging fused in; no prep kernel).
// ---------------------------------------------------------------------------
__global__ void __launch_bounds__(128, 4)
attn_kernel(const float* __restrict__ ent_emb, const float* __restrict__ rec_emb,
            const float* __restrict__ rel_emb,
            const float* __restrict__ w1, const float* __restrict__ b1,
            const float* __restrict__ w2, const float* __restrict__ b2,
            const float* __restrict__ w3, const float* __restrict__ b3,
            const float* __restrict__ wagg, const float* __restrict__ bagg,
            const int* __restrict__ u_ent,  const int* __restrict__ u_heads,
            const int* __restrict__ u_rels, const int* __restrict__ u_tails,
            const int* __restrict__ v_ent,  const int* __restrict__ v_heads,
            const int* __restrict__ v_rels, const int* __restrict__ v_tails) {
    const int tid  = threadIdx.x;
    const int lane = tid & 31;
    const int wid  = tid >> 5;

    __shared__ __nv_bfloat16 W1h_s[DIM][72];
    __shared__ __nv_bfloat16 W2_s [DIM][72];
    __shared__ __nv_bfloat16 A_s  [LL][MM_][72];   // head tiles (warp-private rows)
    __shared__ __nv_bfloat16 Rpre_s[NREL][66];
    __shared__ float b2_s[DIM], w3_s[DIM], bagg_s[DIM];
    __shared__ float pi_s[LL][MM_];
    __shared__ int   rel_s[LL][MM_], tail_s[LL][MM_], e0i_s[MM_];
    __shared__ float2 e0p4[4][32], ap4[LL][4][32];
    __shared__ float  emb_s[3 * DIM];
    __shared__ float  aggp_s[2][DIM];
    __shared__ int    next_s;

    // ---- one-time staging ----
    {
        float* relf = (float*)&A_s[0][0][0];        // 8 KB scratch inside A_s
        for (int i = tid; i < NREL * DIM; i += 128) relf[i] = rel_emb[i];
        for (int i = tid; i < DIM * DIM; i += 128) {
            W1h_s[i >> 6][i & 63] = __float2bfloat16(w1[(i >> 6) * 2 * DIM + (i & 63)]);
            W2_s [i >> 6][i & 63] = __float2bfloat16(w2[i]);
        }
        // waggT bf16: coalesced read, scattered write; idempotent across blocks
        for (int i = tid; i < 3 * DIM * DIM; i += 128) {
            int j = i / (3 * DIM), k = i % (3 * DIM);
            g_waggTb[k * DIM + j] = __float2bfloat16(wagg[i]);
        }
        if (tid < DIM) { b2_s[tid] = b2[tid]; w3_s[tid] = w3[tid]; bagg_s[tid] = bagg[tid]; }
        if (tid == 0) next_s = atomicAdd(&g_ctr, 1);
        __syncthreads();

        // Rpre[rel][j] = b1[j] + rel_emb[rel] . w1[j, 64:128]
        int j = tid >> 1, half = tid & 1;
        float w1r[32];
        const float* wrow = w1 + j * 2 * DIM + DIM + half * 32;
        #pragma unroll
        for (int k = 0; k < 32; k += 4) *(float4*)&w1r[k] = *(const float4*)&wrow[k];
        float bj = b1[j];
        #pragma unroll 4
        for (int rel = 0; rel < NREL; rel++) {
            const float4* re4 = (const float4*)(relf + rel * DIM + half * 32);
            float acc = 0.f;
            #pragma unroll
            for (int q = 0; q < 8; q++) {
                float4 r = re4[q];
                acc += r.x * w1r[q*4] + r.y * w1r[q*4+1] + r.z * w1r[q*4+2] + r.w * w1r[q*4+3];
            }
            acc += __shfl_xor_sync(0xffffffffu, acc, 1);
            if (half == 0) Rpre_s[rel][j] = __float2bfloat16(acc + bj);
        }
    }
    const float b3v = b3[0];
    __syncthreads();   // relf (A_s) dead, Rpre_s / g_waggTb ready

    // fragment addressing
    const int mbase   = wid * 16;
    const int aRow    = lane & 15;
    const int aColOff = (lane >> 4) << 3;
    const int bRowOff = ((lane >> 4) << 3) + (lane & 7);
    const int bKsel   = ((lane >> 3) & 1) << 3;
    const uint32_t baseW1 = smem_u32(&W1h_s[0][0]);
    const uint32_t baseW2 = smem_u32(&W2_s[0][0]);
    const int g  = lane >> 2;
    const int c2 = (lane & 3) * 2;
    const int m0 = mbase + g, m1 = m0 + 8;
    const int h2 = tid >> 6, dd = tid & 63;

    #pragma unroll 1
    while (true) {
        const int pair = next_s;
        if (pair >= PAIRS) break;
        const int side = pair >> 11;
        const int b    = pair & (NB - 1);
        const float* emb0 = side ? ent_emb : rec_emb;
        const int* ent    = side ? v_ent   : u_ent;
        const int* heads  = side ? v_heads : u_heads;
        const int* rels   = side ? v_rels  : u_rels;
        const int* tails  = side ? v_tails : u_tails;

        // ---- front: indices + head gathers (warp-per-row, 2 wavefronts/row) ----
        if (tid < MM_) {
            e0i_s[tid]     = ent  [b * MM_ + tid];
            rel_s [0][tid] = rels [b * MM_ + tid];
            rel_s [1][tid] = rels [NB * MM_ + b * MM_ + tid];
            tail_s[0][tid] = tails[b * MM_ + tid];
            tail_s[1][tid] = tails[NB * MM_ + b * MM_ + tid];
        }
        #pragma unroll
        for (int l = 0; l < LL; l++) {
            #pragma unroll
            for (int batch = 0; batch < 2; batch++) {
                int hidx[8];
                float2 v[8];
                #pragma unroll
                for (int i = 0; i < 8; i++)
                    hidx[i] = heads[l * NB * MM_ + b * MM_ + mbase + batch * 8 + i];
                #pragma unroll
                for (int i = 0; i < 8; i++)
                    v[i] = ((const float2*)(ent_emb + (size_t)hidx[i] * DIM))[lane];
                #pragma unroll
                for (int i = 0; i < 8; i++) {
                    int mm = mbase + batch * 8 + i;
                    *(__nv_bfloat162*)&A_s[l][mm][lane * 2] =
                        __floats2bfloat162_rn(v[i].x, v[i].y);
                }
            }
        }
        __syncthreads();
        if (tid == 0) next_s = atomicAdd(&g_ctr, 1);   // pop-ahead, hidden under GEMMs

        // ---- layer 1 for both hops ----
        #pragma unroll
        for (int l = 0; l < LL; l++) {
            const uint32_t baseA = smem_u32(&A_s[l][0][0]);
            float acc[8][4];
            #pragma unroll
            for (int nt = 0; nt < 8; nt++)
                #pragma unroll
                for (int q = 0; q < 4; q++) acc[nt][q] = 0.f;
            #pragma unroll
            for (int kk = 0; kk < 64; kk += 16) {
                uint32_t a0, a1, a2, a3;
                ldm_x4(a0, a1, a2, a3, baseA + ((mbase + aRow) * 72 + kk + aColOff) * 2);
                #pragma unroll
                for (int ntp = 0; ntp < 4; ntp++) {
                    uint32_t bb0, bb1, bb2, bb3;
                    ldm_x4(bb0, bb1, bb2, bb3,
                           baseW1 + ((ntp * 16 + bRowOff) * 72 + kk + bKsel) * 2);
                    mma_bf16(acc[2 * ntp],     a0, a1, a2, a3, bb0, bb1);
                    mma_bf16(acc[2 * ntp + 1], a0, a1, a2, a3, bb2, bb3);
                }
            }
            int r0 = rel_s[l][m0], r1 = rel_s[l][m1];
            #pragma unroll
            for (int nt = 0; nt < 8; nt++) {
                int j = nt * 8 + c2;
                float2 rp0 = __bfloat1622float2(*(const __nv_bfloat162*)&Rpre_s[r0][j]);
                float2 rp1 = __bfloat1622float2(*(const __nv_bfloat162*)&Rpre_s[r1][j]);
                float v00 = fmaxf(acc[nt][0] + rp0.x, 0.f);
                float v01 = fmaxf(acc[nt][1] + rp0.y, 0.f);
                float v10 = fmaxf(acc[nt][2] + rp1.x, 0.f);
                float v11 = fmaxf(acc[nt][3] + rp1.y, 0.f);
                *(__nv_bfloat162*)&A_s[l][m0][j] = __floats2bfloat162_rn(v00, v01);
                *(__nv_bfloat162*)&A_s[l][m1][j] = __floats2bfloat162_rn(v10, v11);
            }
            __syncwarp();
        }

        // ---- layer 2 + 3 for both hops ----
        #pragma unroll
        for (int l = 0; l < LL; l++) {
            const uint32_t baseA = smem_u32(&A_s[l][0][0]);
            float acc2[8][4];
            #pragma unroll
            for (int nt = 0; nt < 8; nt++)
                #pragma unroll
                for (int q = 0; q < 4; q++) acc2[nt][q] = 0.f;
            #pragma unroll
            for (int kk = 0; kk < 64; kk += 16) {
                uint32_t a0, a1, a2, a3;
                ldm_x4(a0, a1, a2, a3, baseA + ((mbase + aRow) * 72 + kk + aColOff) * 2);
                #pragma unroll
                for (int ntp = 0; ntp < 4; ntp++) {
                    uint32_t bb0, bb1, bb2, bb3;
                    ldm_x4(bb0, bb1, bb2, bb3,
                           baseW2 + ((ntp * 16 + bRowOff) * 72 + kk + bKsel) * 2);
                    mma_bf16(acc2[2 * ntp],     a0, a1, a2, a3, bb0, bb1);
                    mma_bf16(acc2[2 * ntp + 1], a0, a1, a2, a3, bb2, bb3);
                }
            }
            float p0 = 0.f, p1 = 0.f;
            #pragma unroll
            for (int nt = 0; nt < 8; nt++) {
                int j = nt * 8 + c2;
                p0 += fmaxf(acc2[nt][0] + b2_s[j],     0.f) * w3_s[j];
                p0 += fmaxf(acc2[nt][1] + b2_s[j + 1], 0.f) * w3_s[j + 1];
                p1 += fmaxf(acc2[nt][2] + b2_s[j],     0.f) * w3_s[j];
                p1 += fmaxf(acc2[nt][3] + b2_s[j + 1], 0.f) * w3_s[j + 1];
            }
            p0 += __shfl_xor_sync(0xffffffffu, p0, 1);
            p0 += __shfl_xor_sync(0xffffffffu, p0, 2);
            p1 += __shfl_xor_sync(0xffffffffu, p1, 1);
            p1 += __shfl_xor_sync(0xffffffffu, p1, 2);
            if ((lane & 3) == 0) {
                pi_s[l][m0] = sigmoidf_(p0 + b3v);
                pi_s[l][m1] = sigmoidf_(p1 + b3v);
            }
        }
        __syncthreads();

        // ---- softmax both hops, per warp, weights in registers ----
        float w00, w01, w10, w11;
        {
            float v0 = pi_s[0][lane], v1 = pi_s[0][lane + 32];
            float mx = fmaxf(v0, v1);
            #pragma unroll
            for (int o = 16; o; o >>= 1) mx = fmaxf(mx, __shfl_xor_sync(0xffffffffu, mx, o));
            float e0v = __expf(v0 - mx), e1v = __expf(v1 - mx);
            float s = e0v + e1v;
            #pragma unroll
            for (int o = 16; o; o >>= 1) s += __shfl_xor_sync(0xffffffffu, s, o);
            float inv = 1.f / s;
            w00 = e0v * inv; w01 = e1v * inv;
        }
        {
            float v0 = pi_s[1][lane], v1 = pi_s[1][lane + 32];
            float mx = fmaxf(v0, v1);
            #pragma unroll
            for (int o = 16; o; o >>= 1) mx = fmaxf(mx, __shfl_xor_sync(0xffffffffu, mx, o));
            float e0v = __expf(v0 - mx), e1v = __expf(v1 - mx);
            float s = e0v + e1v;
            #pragma unroll
            for (int o = 16; o; o >>= 1) s += __shfl_xor_sync(0xffffffffu, s, o);
            float inv = 1.f / s;
            w10 = e0v * inv; w11 = e1v * inv;
        }

        // ---- tail/e0 gathers: warp quarter = 16 rows, lane = dim pair ----
        {
            const int mq = wid * 16;
            float2 a0acc = make_float2(0.f, 0.f);
            float2 a1acc = make_float2(0.f, 0.f);
            float2 e0acc = make_float2(0.f, 0.f);
            #pragma unroll
            for (int batch = 0; batch < 2; batch++) {
                float2 v0[8], v1[8], ve[8];
                #pragma unroll
                for (int i = 0; i < 8; i++) {
                    int mm = mq + batch * 8 + i;
                    v0[i] = ((const float2*)(ent_emb + (size_t)tail_s[0][mm] * DIM))[lane];
                    v1[i] = ((const float2*)(ent_emb + (size_t)tail_s[1][mm] * DIM))[lane];
                    ve[i] = ((const float2*)(emb0    + (size_t)e0i_s[mm]     * DIM))[lane];
                }
                #pragma unroll
                for (int i = 0; i < 8; i++) {
                    int mm = mq + batch * 8 + i;
                    float wv0 = (wid < 2) ? __shfl_sync(0xffffffffu, w00, mm)
                                          : __shfl_sync(0xffffffffu, w01, mm - 32);
                    float wv1 = (wid < 2) ? __shfl_sync(0xffffffffu, w10, mm)
                                          : __shfl_sync(0xffffffffu, w11, mm - 32);
                    a0acc.x = fmaf(wv0, v0[i].x, a0acc.x);
                    a0acc.y = fmaf(wv0, v0[i].y, a0acc.y);
                    a1acc.x = fmaf(wv1, v1[i].x, a1acc.x);
                    a1acc.y = fmaf(wv1, v1[i].y, a1acc.y);
                    e0acc.x += ve[i].x;
                    e0acc.y += ve[i].y;
                }
            }
            ap4[0][wid][lane] = a0acc;
            ap4[1][wid][lane] = a1acc;
            e0p4[wid][lane]   = e0acc;
        }
        __syncthreads();

        // ---- build emb[192] ----
        if (tid < 96) {
            int seg = tid >> 5, p = tid & 31;
            float2 s = make_float2(0.f, 0.f);
            #pragma unroll
            for (int w = 0; w < 4; w++) {
                float2 v = (seg == 0) ? e0p4[w][p] : ap4[seg - 1][w][p];
                s.x += v.x; s.y += v.y;
            }
            if (seg == 0) { s.x *= (1.f / 64.f); s.y *= (1.f / 64.f); }
            ((float2*)emb_s)[tid] = s;
        }
        __syncthreads();

        // ---- agg GEMV: bf16 waggT, colwise-coalesced (validated R7 layout) ----
        {
            float acc = 0.f;
            const __nv_bfloat16* wt = g_waggTb + (size_t)(h2 * 96) * DIM + dd;
            #pragma unroll 12
            for (int k = 0; k < 96; k++)
                acc = fmaf(emb_s[h2 * 96 + k], __bfloat162float(wt[(size_t)k * DIM]), acc);
            aggp_s[h2][dd] = acc;
        }
        __syncthreads();
        if (tid < 64)
            g_side[side][b][tid] = sigmoidf_(aggp_s[0][tid] + aggp_s[1][tid] + bagg_s[tid]);
        __syncthreads();   // everyone done with smem; next_s consumed at top
    }

    // ---- self-cleaning exit: last block resets the work counter ----
    if (tid == 0) {
        int old = atomicAdd(&g_exit, 1);
        if (old == GRIDP - 1) {
            g_ctr = 0;
            __threadfence();
            g_exit = 0;
        }
    }
}

// ---------------------------------------------------------------------------
// Combine: out[b] = sigmoid(users[b] · items[b]); one warp per b.
// ---------------------------------------------------------------------------
__global__ void combine_kernel(float* __restrict__ out) {
    int gw   = (blockIdx.x * blockDim.x + threadIdx.x) >> 5;
    int lane = threadIdx.x & 31;
    if (gw >= NB) return;
    float s = g_side[0][gw][lane]      * g_side[1][gw][lane]
            + g_side[0][gw][lane + 32] * g_side[1][gw][lane + 32];
    #pragma unroll
    for (int o = 16; o; o >>= 1) s += __shfl_down_sync(0xffffffffu, s, o);
    if (lane == 0) out[gw] = sigmoidf_(s);
}

extern "C" void kernel_launch(void* const* d_in, const int* in_sizes, int n_in,
                              void* d_out, int out_size) {
    const float* ent_emb = (const float*)d_in[0];
    const float* rec_emb = (const float*)d_in[1];
    const float* rel_emb = (const float*)d_in[2];
    const float* w1      = (const float*)d_in[3];
    const float* b1      = (const float*)d_in[4];
    const float* w2      = (const float*)d_in[5];
    const float* b2      = (const float*)d_in[6];
    const float* w3      = (const float*)d_in[7];
    const float* b3      = (const float*)d_in[8];
    const float* wagg    = (const float*)d_in[9];
    const float* bagg    = (const float*)d_in[10];
    const int*   u_ent   = (const int*)d_in[11];
    const int*   u_heads = (const int*)d_in[12];
    const int*   u_rels  = (const int*)d_in[13];
    const int*   u_tails = (const int*)d_in[14];
    const int*   v_ent   = (const int*)d_in[15];
    const int*   v_heads = (const int*)d_in[16];
    const int*   v_rels  = (const int*)d_in[17];
    const int*   v_tails = (const int*)d_in[18];

    attn_kernel<<<GRIDP, 128>>>(ent_emb, rec_emb, rel_emb, w1, b1, w2, b2, w3, b3,
                                wagg, bagg,
                                u_ent, u_heads, u_rels, u_tails,
                                v_ent, v_heads, v_rels, v_tails);
    combine_kernel<<<NB / 8, 256>>>((float*)d_out);
}

// round 10
// speedup vs baseline: 5.6590x; 5.6590x over previous
#include <cuda_runtime.h>
#include <cuda_bf16.h>
#include <cstdint>

#define DIM   64
#define MM_   64
#define NB    2048
#define LL    2
#define NREL  32
#define PAIRS (2 * NB)
#define GRIDP 592          // 148 SM * 4 blocks, all resident

// Scratch (no dynamic allocation allowed)
__device__ __nv_bfloat16 g_RpreB[NREL * DIM];      // [rel][j], bf16
__device__ __nv_bfloat16 g_W1b[DIM * DIM];         // head half of w1, bf16
__device__ __nv_bfloat16 g_W2b[DIM * DIM];
__device__ __nv_bfloat16 g_waggTb[3 * DIM * DIM];  // [k][j], bf16
__device__ float         g_side[2][NB][DIM];
__device__ int           g_ctr;                    // work-stealing counter

__device__ __forceinline__ float sigmoidf_(float x) {
    return 1.f / (1.f + __expf(-x));
}
__device__ __forceinline__ uint32_t smem_u32(const void* p) {
    return (uint32_t)__cvta_generic_to_shared(p);
}
__device__ __forceinline__ void ldm_x4(uint32_t& r0, uint32_t& r1, uint32_t& r2, uint32_t& r3, uint32_t a) {
    asm volatile("ldmatrix.sync.aligned.m8n8.x4.shared.b16 {%0,%1,%2,%3},[%4];\n"
                 : "=r"(r0), "=r"(r1), "=r"(r2), "=r"(r3) : "r"(a));
}
__device__ __forceinline__ void mma_bf16(float* d, uint32_t a0, uint32_t a1, uint32_t a2, uint32_t a3,
                                         uint32_t b0, uint32_t b1) {
    asm volatile("mma.sync.aligned.m16n8k16.row.col.f32.bf16.bf16.f32 "
                 "{%0,%1,%2,%3},{%4,%5,%6,%7},{%8,%9},{%0,%1,%2,%3};\n"
                 : "+f"(d[0]), "+f"(d[1]), "+f"(d[2]), "+f"(d[3])
                 : "r"(a0), "r"(a1), "r"(a2), "r"(a3), "r"(b0), "r"(b1));
}

// ---------------------------------------------------------------------------
// Prep: blocks 0..31 Rpre(bf16); 32..39 bf16 weights; 40..55 waggT(bf16).
// Block 40 also resets the work counter.
// ---------------------------------------------------------------------------
__global__ void __launch_bounds__(128)
prep_kernel(const float* __restrict__ rel_emb,
            const float* __restrict__ w1,
            const float* __restrict__ b1,
            const float* __restrict__ w2,
            const float* __restrict__ wagg) {
    const int blk = blockIdx.x;
    const int t   = threadIdx.x;
    if (blk < NREL) {
        int j = t >> 1, half = t & 1;
        const float* wr = w1 + j * 2 * DIM + DIM + half * 32;
        const float* re = rel_emb + blk * DIM + half * 32;
        float acc = 0.f;
        #pragma unroll
        for (int k = 0; k < 32; k++) acc = fmaf(re[k], wr[k], acc);
        acc += __shfl_xor_sync(0xffffffffu, acc, 1);
        if (half == 0) g_RpreB[blk * DIM + j] = __float2bfloat16(acc + b1[j]);
    } else if (blk < 40) {
        #pragma unroll
        for (int i = (blk - 32) * 128 + t; i < DIM * DIM; i += 1024) {
            g_W1b[i] = __float2bfloat16(w1[(i >> 6) * 2 * DIM + (i & 63)]);
            g_W2b[i] = __float2bfloat16(w2[i]);
        }
    } else {
        if (blk == 40 && t == 0) g_ctr = 0;
        #pragma unroll
        for (int i = (blk - 40) * 128 + t; i < 3 * DIM * DIM; i += 2048) {
            int k = i >> 6, j = i & 63;
            g_waggTb[i] = __float2bfloat16(wagg[j * 3 * DIM + k]);
        }
    }
}

// ---------------------------------------------------------------------------
// Attention + aggregation: persistent, work-stealing over 4096 (side,b) pairs.
// 592 blocks x 128 threads, 4 warps.
// ---------------------------------------------------------------------------
__global__ void __launch_bounds__(128, 4)
attn_kernel(const float* __restrict__ ent_emb, const float* __restrict__ rec_emb,
            const float* __restrict__ b2, const float* __restrict__ w3,
            const float* __restrict__ b3, const float* __restrict__ bagg,
            const int* __restrict__ u_ent,  const int* __restrict__ u_heads,
            const int* __restrict__ u_rels, const int* __restrict__ u_tails,
            const int* __restrict__ v_ent,  const int* __restrict__ v_heads,
            const int* __restrict__ v_rels, const int* __restrict__ v_tails) {
    const int tid  = threadIdx.x;
    const int lane = tid & 31;
    const int wid  = tid >> 5;

    __shared__ __nv_bfloat16 W1h_s[DIM][72];
    __shared__ __nv_bfloat16 W2_s [DIM][72];
    __shared__ __nv_bfloat16 A_s  [LL][MM_][72];   // head tiles; Y1 in place
    __shared__ __nv_bfloat16 Rpre_s[NREL][66];
    __shared__ float b2_s[DIM], w3_s[DIM], bagg_s[DIM];
    __shared__ float pi_s[LL][MM_];
    __shared__ int   rel_s[LL][MM_], tail_s[LL][MM_], e0i_s[MM_];
    __shared__ float2 e0p4[4][32], ap4[LL][4][32];
    __shared__ float  emb_s[3 * DIM];
    __shared__ float  aggp_s[2][DIM];
    __shared__ int    next_s;

    // one-time staging
    for (int i = tid; i < DIM * DIM; i += 128) {
        W1h_s[i >> 6][i & 63] = g_W1b[i];
        W2_s [i >> 6][i & 63] = g_W2b[i];
    }
    for (int i = tid; i < NREL * DIM / 2; i += 128) {
        int r = i >> 5, j = (i & 31) * 2;
        *(uint32_t*)&Rpre_s[r][j] = *(const uint32_t*)&g_RpreB[r * DIM + j];
    }
    if (tid < DIM) { b2_s[tid] = b2[tid]; w3_s[tid] = w3[tid]; bagg_s[tid] = bagg[tid]; }
    if (tid == 0) next_s = atomicAdd(&g_ctr, 1);
    const float b3v = b3[0];
    __syncthreads();

    // fragment addressing
    const int mbase   = wid * 16;
    const int aRow    = lane & 15;
    const int aColOff = (lane >> 4) << 3;
    const int bRowOff = ((lane >> 4) << 3) + (lane & 7);
    const int bKsel   = ((lane >> 3) & 1) << 3;
    const uint32_t baseW1 = smem_u32(&W1h_s[0][0]);
    const uint32_t baseW2 = smem_u32(&W2_s[0][0]);
    const int g  = lane >> 2;
    const int c2 = (lane & 3) * 2;
    const int m0 = mbase + g, m1 = m0 + 8;
    const int h2 = tid >> 6, dd = tid & 63;
    const int rsel = lane >> 4;     // row within pair (head gather)
    const int csel = lane & 15;     // float4 chunk within row

    #pragma unroll 1
    while (true) {
        const int pair = next_s;            // uniform: all threads past a barrier
        if (pair >= PAIRS) break;
        const int side = pair >> 11;
        const int b    = pair & (NB - 1);
        const float* emb0 = side ? ent_emb : rec_emb;
        const int* ent    = side ? v_ent   : u_ent;
        const int* heads  = side ? v_heads : u_heads;
        const int* rels   = side ? v_rels  : u_rels;
        const int* tails  = side ? v_tails : u_tails;

        // ---- front: indices + head gathers for BOTH hops ----
        // Head gather: warp covers rows [mbase, mbase+16) as 8 row-pairs.
        // Per LDG.128: 2 rows x 256B = 4 L1 wavefronts (vs 32 in the old map).
        if (tid < MM_) {
            e0i_s[tid]     = ent  [b * MM_ + tid];
            rel_s [0][tid] = rels [b * MM_ + tid];
            rel_s [1][tid] = rels [NB * MM_ + b * MM_ + tid];
            tail_s[0][tid] = tails[b * MM_ + tid];
            tail_s[1][tid] = tails[NB * MM_ + b * MM_ + tid];
        }
        #pragma unroll
        for (int l = 0; l < LL; l++) {
            #pragma unroll
            for (int half = 0; half < 2; half++) {
                float4 v[4];
                int rows[4];
                #pragma unroll
                for (int p = 0; p < 4; p++) {
                    rows[p] = mbase + (half * 4 + p) * 2 + rsel;
                    int hidx = heads[l * NB * MM_ + b * MM_ + rows[p]];
                    v[p] = ((const float4*)(ent_emb + (size_t)hidx * DIM))[csel];
                }
                #pragma unroll
                for (int p = 0; p < 4; p++) {
                    __nv_bfloat162 pk[2];
                    pk[0] = __floats2bfloat162_rn(v[p].x, v[p].y);
                    pk[1] = __floats2bfloat162_rn(v[p].z, v[p].w);
                    *(uint2*)&A_s[l][rows[p]][csel * 4] = *(uint2*)pk;
                }
            }
        }
        __syncthreads();
        if (tid == 0) next_s = atomicAdd(&g_ctr, 1);   // pop-ahead, hidden under GEMMs

        // ---- layer 1 for both hops ----
        #pragma unroll
        for (int l = 0; l < LL; l++) {
            const uint32_t baseA = smem_u32(&A_s[l][0][0]);
            float acc[8][4];
            #pragma unroll
            for (int nt = 0; nt < 8; nt++)
                #pragma unroll
                for (int q = 0; q < 4; q++) acc[nt][q] = 0.f;
            #pragma unroll
            for (int kk = 0; kk < 64; kk += 16) {
                uint32_t a0, a1, a2, a3;
                ldm_x4(a0, a1, a2, a3, baseA + ((mbase + aRow) * 72 + kk + aColOff) * 2);
                #pragma unroll
                for (int ntp = 0; ntp < 4; ntp++) {
                    uint32_t bb0, bb1, bb2, bb3;
                    ldm_x4(bb0, bb1, bb2, bb3,
                           baseW1 + ((ntp * 16 + bRowOff) * 72 + kk + bKsel) * 2);
                    mma_bf16(acc[2 * ntp],     a0, a1, a2, a3, bb0, bb1);
                    mma_bf16(acc[2 * ntp + 1], a0, a1, a2, a3, bb2, bb3);
                }
            }
            int r0 = rel_s[l][m0], r1 = rel_s[l][m1];
            #pragma unroll
            for (int nt = 0; nt < 8; nt++) {
                int j = nt * 8 + c2;
                float2 rp0 = __bfloat1622float2(*(const __nv_bfloat162*)&Rpre_s[r0][j]);
                float2 rp1 = __bfloat1622float2(*(const __nv_bfloat162*)&Rpre_s[r1][j]);
                float v00 = fmaxf(acc[nt][0] + rp0.x, 0.f);
                float v01 = fmaxf(acc[nt][1] + rp0.y, 0.f);
                float v10 = fmaxf(acc[nt][2] + rp1.x, 0.f);
                float v11 = fmaxf(acc[nt][3] + rp1.y, 0.f);
                *(__nv_bfloat162*)&A_s[l][m0][j] = __floats2bfloat162_rn(v00, v01);
                *(__nv_bfloat162*)&A_s[l][m1][j] = __floats2bfloat162_rn(v10, v11);
            }
            __syncwarp();
        }

        // ---- layer 2 + 3 for both hops ----
        #pragma unroll
        for (int l = 0; l < LL; l++) {
            const uint32_t baseA = smem_u32(&A_s[l][0][0]);
            float acc2[8][4];
            #pragma unroll
            for (int nt = 0; nt < 8; nt++)
                #pragma unroll
                for (int q = 0; q < 4; q++) acc2[nt][q] = 0.f;
            #pragma unroll
            for (int kk = 0; kk < 64; kk += 16) {
                uint32_t a0, a1, a2, a3;
                ldm_x4(a0, a1, a2, a3, baseA + ((mbase + aRow) * 72 + kk + aColOff) * 2);
                #pragma unroll
                for (int ntp = 0; ntp < 4; ntp++) {
                    uint32_t bb0, bb1, bb2, bb3;
                    ldm_x4(bb0, bb1, bb2, bb3,
                           baseW2 + ((ntp * 16 + bRowOff) * 72 + kk + bKsel) * 2);
                    mma_bf16(acc2[2 * ntp],     a0, a1, a2, a3, bb0, bb1);
                    mma_bf16(acc2[2 * ntp + 1], a0, a1, a2, a3, bb2, bb3);
                }
            }
            float p0 = 0.f, p1 = 0.f;
            #pragma unroll
            for (int nt = 0; nt < 8; nt++) {
                int j = nt * 8 + c2;
                p0 += fmaxf(acc2[nt][0] + b2_s[j],     0.f) * w3_s[j];
                p0 += fmaxf(acc2[nt][1] + b2_s[j + 1], 0.f) * w3_s[j + 1];
                p1 += fmaxf(acc2[nt][2] + b2_s[j],     0.f) * w3_s[j];
                p1 += fmaxf(acc2[nt][3] + b2_s[j + 1], 0.f) * w3_s[j + 1];
            }
            p0 += __shfl_xor_sync(0xffffffffu, p0, 1);
            p0 += __shfl_xor_sync(0xffffffffu, p0, 2);
            p1 += __shfl_xor_sync(0xffffffffu, p1, 1);
            p1 += __shfl_xor_sync(0xffffffffu, p1, 2);
            if ((lane & 3) == 0) {
                pi_s[l][m0] = sigmoidf_(p0 + b3v);
                pi_s[l][m1] = sigmoidf_(p1 + b3v);
            }
        }
        __syncthreads();

        // ---- softmax both hops, per warp, weights in registers ----
        float w00, w01, w10, w11;
        {
            float v0 = pi_s[0][lane], v1 = pi_s[0][lane + 32];
            float mx = fmaxf(v0, v1);
            #pragma unroll
            for (int o = 16; o; o >>= 1) mx = fmaxf(mx, __shfl_xor_sync(0xffffffffu, mx, o));
            float e0v = __expf(v0 - mx), e1v = __expf(v1 - mx);
            float s = e0v + e1v;
            #pragma unroll
            for (int o = 16; o; o >>= 1) s += __shfl_xor_sync(0xffffffffu, s, o);
            float inv = 1.f / s;
            w00 = e0v * inv; w01 = e1v * inv;
        }
        {
            float v0 = pi_s[1][lane], v1 = pi_s[1][lane + 32];
            float mx = fmaxf(v0, v1);
            #pragma unroll
            for (int o = 16; o; o >>= 1) mx = fmaxf(mx, __shfl_xor_sync(0xffffffffu, mx, o));
            float e0v = __expf(v0 - mx), e1v = __expf(v1 - mx);
            float s = e0v + e1v;
            #pragma unroll
            for (int o = 16; o; o >>= 1) s += __shfl_xor_sync(0xffffffffu, s, o);
            float inv = 1.f / s;
            w10 = e0v * inv; w11 = e1v * inv;
        }

        // ---- gathers: warp quarter = 16 neighbor rows, lane = dim pair ----
        {
            const int mq = wid * 16;
            float2 a0acc = make_float2(0.f, 0.f);
            float2 a1acc = make_float2(0.f, 0.f);
            float2 e0acc = make_float2(0.f, 0.f);
            #pragma unroll
            for (int batch = 0; batch < 2; batch++) {
                float2 v0[8], v1[8], ve[8];
                #pragma unroll
                for (int i = 0; i < 8; i++) {
                    int mm = mq + batch * 8 + i;
                    v0[i] = ((const float2*)(ent_emb + (size_t)tail_s[0][mm] * DIM))[lane];
                    v1[i] = ((const float2*)(ent_emb + (size_t)tail_s[1][mm] * DIM))[lane];
                    ve[i] = ((const float2*)(emb0    + (size_t)e0i_s[mm]     * DIM))[lane];
                }
                #pragma unroll
                for (int i = 0; i < 8; i++) {
                    int mm = mq + batch * 8 + i;
                    float wv0 = (wid < 2) ? __shfl_sync(0xffffffffu, w00, mm)
                                          : __shfl_sync(0xffffffffu, w01, mm - 32);
                    float wv1 = (wid < 2) ? __shfl_sync(0xffffffffu, w10, mm)
                                          : __shfl_sync(0xffffffffu, w11, mm - 32);
                    a0acc.x = fmaf(wv0, v0[i].x, a0acc.x);
                    a0acc.y = fmaf(wv0, v0[i].y, a0acc.y);
                    a1acc.x = fmaf(wv1, v1[i].x, a1acc.x);
                    a1acc.y = fmaf(wv1, v1[i].y, a1acc.y);
                    e0acc.x += ve[i].x;
                    e0acc.y += ve[i].y;
                }
            }
            ap4[0][wid][lane] = a0acc;
            ap4[1][wid][lane] = a1acc;
            e0p4[wid][lane]   = e0acc;
        }
        __syncthreads();

        // ---- build emb[192] ----
        if (tid < 96) {
            int seg = tid >> 5, p = tid & 31;
            float2 s = make_float2(0.f, 0.f);
            #pragma unroll
            for (int w = 0; w < 4; w++) {
                float2 v = (seg == 0) ? e0p4[w][p] : ap4[seg - 1][w][p];
                s.x += v.x; s.y += v.y;
            }
            if (seg == 0) { s.x *= (1.f / 64.f); s.y *= (1.f / 64.f); }
            ((float2*)emb_s)[tid] = s;
        }
        __syncthreads();

        // ---- agg GEMV ----
        {
            float acc = 0.f;
            const __nv_bfloat16* wt = g_waggTb + (size_t)(h2 * 96) * DIM + dd;
            #pragma unroll 12
            for (int k = 0; k < 96; k++)
                acc = fmaf(emb_s[h2 * 96 + k], __bfloat162float(wt[(size_t)k * DIM]), acc);
            aggp_s[h2][dd] = acc;
        }
        __syncthreads();
        if (tid < 64)
            g_side[side][b][tid] = sigmoidf_(aggp_s[0][tid] + aggp_s[1][tid] + bagg_s[tid]);
        __syncthreads();   // everyone done with smem + next_s consumed next at top
    }
}

// ---------------------------------------------------------------------------
// Combine: out[b] = sigmoid(users[b] · items[b]); one warp per b.
// ---------------------------------------------------------------------------
__global__ void combine_kernel(float* __restrict__ out) {
    int gw   = (blockIdx.x * blockDim.x + threadIdx.x) >> 5;
    int lane = threadIdx.x & 31;
    if (gw >= NB) return;
    float s = g_side[0][gw][lane]      * g_side[1][gw][lane]
            + g_side[0][gw][lane + 32] * g_side[1][gw][lane + 32];
    #pragma unroll
    for (int o = 16; o; o >>= 1) s += __shfl_down_sync(0xffffffffu, s, o);
    if (lane == 0) out[gw] = sigmoidf_(s);
}

extern "C" void kernel_launch(void* const* d_in, const int* in_sizes, int n_in,
                              void* d_out, int out_size) {
    const float* ent_emb = (const float*)d_in[0];
    const float* rec_emb = (const float*)d_in[1];
    const float* rel_emb = (const float*)d_in[2];
    const float* w1      = (const float*)d_in[3];
    const float* b1      = (const float*)d_in[4];
    const float* w2      = (const float*)d_in[5];
    const float* b2      = (const float*)d_in[6];
    const float* w3      = (const float*)d_in[7];
    const float* b3      = (const float*)d_in[8];
    const float* wagg    = (const float*)d_in[9];
    const float* bagg    = (const float*)d_in[10];
    const int*   u_ent   = (const int*)d_in[11];
    const int*   u_heads = (const int*)d_in[12];
    const int*   u_rels  = (const int*)d_in[13];
    const int*   u_tails = (const int*)d_in[14];
    const int*   v_ent   = (const int*)d_in[15];
    const int*   v_heads = (const int*)d_in[16];
    const int*   v_rels  = (const int*)d_in[17];
    const int*   v_tails = (const int*)d_in[18];

    prep_kernel<<<56, 128>>>(rel_emb, w1, b1, w2, wagg);
    attn_kernel<<<GRIDP, 128>>>(ent_emb, rec_emb, b2, w3, b3, bagg,
                                u_ent, u_heads, u_rels, u_tails,
                                v_ent, v_heads, v_rels, v_tails);
    combine_kernel<<<NB / 8, 256>>>((float*)d_out);
}

// round 11
// speedup vs baseline: 5.9037x; 1.0432x over previous
#include <cuda_runtime.h>
#include <cuda_bf16.h>
#include <cstdint>

#define DIM   64
#define MM_   64
#define NB    2048
#define LL    2
#define NREL  32
#define PAIRS (2 * NB)
#define GRIDP 592          // 148 SM * 4 blocks, all resident

// Scratch (no dynamic allocation allowed)
__device__ __nv_bfloat16 g_RpreB[NREL * DIM];      // [rel][j], bf16
__device__ __nv_bfloat16 g_W1b[DIM * DIM];         // head half of w1, bf16
__device__ __nv_bfloat16 g_W2b[DIM * DIM];
__device__ __nv_bfloat16 g_waggTb[3 * DIM * DIM];  // [k][j], bf16
__device__ float         g_side[2][NB][DIM];
__device__ int           g_ctr;                    // work-stealing counter

__device__ __forceinline__ float sigmoidf_(float x) {
    return 1.f / (1.f + __expf(-x));
}
__device__ __forceinline__ uint32_t smem_u32(const void* p) {
    return (uint32_t)__cvta_generic_to_shared(p);
}
__device__ __forceinline__ uint32_t pack_relu2(float a, float b) {
    __nv_bfloat162 p = __floats2bfloat162_rn(fmaxf(a, 0.f), fmaxf(b, 0.f));
    return *(uint32_t*)&p;
}
__device__ __forceinline__ void ldm_x4(uint32_t& r0, uint32_t& r1, uint32_t& r2, uint32_t& r3, uint32_t a) {
    asm volatile("ldmatrix.sync.aligned.m8n8.x4.shared.b16 {%0,%1,%2,%3},[%4];\n"
                 : "=r"(r0), "=r"(r1), "=r"(r2), "=r"(r3) : "r"(a));
}
__device__ __forceinline__ void mma_bf16(float* d, uint32_t a0, uint32_t a1, uint32_t a2, uint32_t a3,
                                         uint32_t b0, uint32_t b1) {
    asm volatile("mma.sync.aligned.m16n8k16.row.col.f32.bf16.bf16.f32 "
                 "{%0,%1,%2,%3},{%4,%5,%6,%7},{%8,%9},{%0,%1,%2,%3};\n"
                 : "+f"(d[0]), "+f"(d[1]), "+f"(d[2]), "+f"(d[3])
                 : "r"(a0), "r"(a1), "r"(a2), "r"(a3), "r"(b0), "r"(b1));
}

// ---------------------------------------------------------------------------
// Prep: blocks 0..31 Rpre(bf16); 32..39 bf16 weights; 40..55 waggT(bf16).
// Block 40 also resets the work counter.
// ---------------------------------------------------------------------------
__global__ void __launch_bounds__(128)
prep_kernel(const float* __restrict__ rel_emb,
            const float* __restrict__ w1,
            const float* __restrict__ b1,
            const float* __restrict__ w2,
            const float* __restrict__ wagg) {
    const int blk = blockIdx.x;
    const int t   = threadIdx.x;
    if (blk < NREL) {
        int j = t >> 1, half = t & 1;
        const float* wr = w1 + j * 2 * DIM + DIM + half * 32;
        const float* re = rel_emb + blk * DIM + half * 32;
        float acc = 0.f;
        #pragma unroll
        for (int k = 0; k < 32; k++) acc = fmaf(re[k], wr[k], acc);
        acc += __shfl_xor_sync(0xffffffffu, acc, 1);
        if (half == 0) g_RpreB[blk * DIM + j] = __float2bfloat16(acc + b1[j]);
    } else if (blk < 40) {
        #pragma unroll
        for (int i = (blk - 32) * 128 + t; i < DIM * DIM; i += 1024) {
            g_W1b[i] = __float2bfloat16(w1[(i >> 6) * 2 * DIM + (i & 63)]);
            g_W2b[i] = __float2bfloat16(w2[i]);
        }
    } else {
        if (blk == 40 && t == 0) g_ctr = 0;
        #pragma unroll
        for (int i = (blk - 40) * 128 + t; i < 3 * DIM * DIM; i += 2048) {
            int k = i >> 6, j = i & 63;
            g_waggTb[i] = __float2bfloat16(wagg[j * 3 * DIM + k]);
        }
    }
}

// ---------------------------------------------------------------------------
// Attention + aggregation: persistent, work-stealing over 4096 (side,b) pairs.
// 592 blocks x 128 threads, 4 warps. Layer1->Layer2 fused in registers.
// ---------------------------------------------------------------------------
__global__ void __launch_bounds__(128, 4)
attn_kernel(const float* __restrict__ ent_emb, const float* __restrict__ rec_emb,
            const float* __restrict__ b2, const float* __restrict__ w3,
            const float* __restrict__ b3, const float* __restrict__ bagg,
            const int* __restrict__ u_ent,  const int* __restrict__ u_heads,
            const int* __restrict__ u_rels, const int* __restrict__ u_tails,
            const int* __restrict__ v_ent,  const int* __restrict__ v_heads,
            const int* __restrict__ v_rels, const int* __restrict__ v_tails) {
    const int tid  = threadIdx.x;
    const int lane = tid & 31;
    const int wid  = tid >> 5;

    __shared__ __nv_bfloat16 W1h_s[DIM][72];
    __shared__ __nv_bfloat16 W2_s [DIM][72];
    __shared__ __nv_bfloat16 A_s  [LL][MM_][72];   // head tiles
    __shared__ __nv_bfloat16 Rpre_s[NREL][66];
    __shared__ float b2_s[DIM], w3_s[DIM], bagg_s[DIM];
    __shared__ float pi_s[LL][MM_];
    __shared__ int   rel_s[LL][MM_], tail_s[LL][MM_], e0i_s[MM_];
    __shared__ float2 e0p4[4][32], ap4[LL][4][32];
    __shared__ float  emb_s[3 * DIM];
    __shared__ float  aggp_s[2][DIM];
    __shared__ int    next_s;

    // one-time staging
    for (int i = tid; i < DIM * DIM; i += 128) {
        W1h_s[i >> 6][i & 63] = g_W1b[i];
        W2_s [i >> 6][i & 63] = g_W2b[i];
    }
    for (int i = tid; i < NREL * DIM / 2; i += 128) {
        int r = i >> 5, j = (i & 31) * 2;
        *(uint32_t*)&Rpre_s[r][j] = *(const uint32_t*)&g_RpreB[r * DIM + j];
    }
    if (tid < DIM) { b2_s[tid] = b2[tid]; w3_s[tid] = w3[tid]; bagg_s[tid] = bagg[tid]; }
    if (tid == 0) next_s = atomicAdd(&g_ctr, 1);
    const float b3v = b3[0];
    __syncthreads();

    // fragment addressing
    const int mbase   = wid * 16;
    const int aRow    = lane & 15;
    const int aColOff = (lane >> 4) << 3;
    const int bRowOff = ((lane >> 4) << 3) + (lane & 7);
    const int bKsel   = ((lane >> 3) & 1) << 3;
    const uint32_t baseW1 = smem_u32(&W1h_s[0][0]);
    const uint32_t baseW2 = smem_u32(&W2_s[0][0]);
    const int g  = lane >> 2;
    const int c2 = (lane & 3) * 2;
    const int m0 = mbase + g, m1 = m0 + 8;
    const int h2 = tid >> 6, dd = tid & 63;
    const int rsel = lane >> 4;     // row within pair (head gather)
    const int csel = lane & 15;     // float4 chunk within row

    #pragma unroll 1
    while (true) {
        const int pair = next_s;            // uniform: all threads past a barrier
        if (pair >= PAIRS) break;
        const int side = pair >> 11;
        const int b    = pair & (NB - 1);
        const float* emb0 = side ? ent_emb : rec_emb;
        const int* ent    = side ? v_ent   : u_ent;
        const int* heads  = side ? v_heads : u_heads;
        const int* rels   = side ? v_rels  : u_rels;
        const int* tails  = side ? v_tails : u_tails;

        // ---- front: indices + head gathers for BOTH hops ----
        if (tid < MM_) {
            e0i_s[tid]     = ent  [b * MM_ + tid];
            rel_s [0][tid] = rels [b * MM_ + tid];
            rel_s [1][tid] = rels [NB * MM_ + b * MM_ + tid];
            tail_s[0][tid] = tails[b * MM_ + tid];
            tail_s[1][tid] = tails[NB * MM_ + b * MM_ + tid];
        }
        #pragma unroll
        for (int l = 0; l < LL; l++) {
            #pragma unroll
            for (int half = 0; half < 2; half++) {
                float4 v[4];
                int rows[4];
                #pragma unroll
                for (int p = 0; p < 4; p++) {
                    rows[p] = mbase + (half * 4 + p) * 2 + rsel;
                    int hidx = heads[l * NB * MM_ + b * MM_ + rows[p]];
                    v[p] = ((const float4*)(ent_emb + (size_t)hidx * DIM))[csel];
                }
                #pragma unroll
                for (int p = 0; p < 4; p++) {
                    __nv_bfloat162 pk[2];
                    pk[0] = __floats2bfloat162_rn(v[p].x, v[p].y);
                    pk[1] = __floats2bfloat162_rn(v[p].z, v[p].w);
                    *(uint2*)&A_s[l][rows[p]][csel * 4] = *(uint2*)pk;
                }
            }
        }
        __syncthreads();
        if (tid == 0) next_s = atomicAdd(&g_ctr, 1);   // pop-ahead, hidden under GEMMs

        // ---- per hop: layer1 GEMM -> register relayout -> layer2 GEMM -> pi ----
        #pragma unroll
        for (int l = 0; l < LL; l++) {
            const uint32_t baseA = smem_u32(&A_s[l][0][0]);

            // layer 1
            float acc[8][4];
            #pragma unroll
            for (int nt = 0; nt < 8; nt++)
                #pragma unroll
                for (int q = 0; q < 4; q++) acc[nt][q] = 0.f;
            #pragma unroll
            for (int kk = 0; kk < 64; kk += 16) {
                uint32_t a0, a1, a2, a3;
                ldm_x4(a0, a1, a2, a3, baseA + ((mbase + aRow) * 72 + kk + aColOff) * 2);
                #pragma unroll
                for (int ntp = 0; ntp < 4; ntp++) {
                    uint32_t bb0, bb1, bb2, bb3;
                    ldm_x4(bb0, bb1, bb2, bb3,
                           baseW1 + ((ntp * 16 + bRowOff) * 72 + kk + bKsel) * 2);
                    mma_bf16(acc[2 * ntp],     a0, a1, a2, a3, bb0, bb1);
                    mma_bf16(acc[2 * ntp + 1], a0, a1, a2, a3, bb2, bb3);
                }
            }

            // epilogue -> layer-2 A fragments in registers (C-layout == A-layout)
            uint32_t ya0[4], ya1[4], ya2[4], ya3[4];
            {
                int r0 = rel_s[l][m0], r1 = rel_s[l][m1];
                #pragma unroll
                for (int t = 0; t < 4; t++) {
                    int je = 16 * t + c2, jo = je + 8;
                    float2 rp0e = __bfloat1622float2(*(const __nv_bfloat162*)&Rpre_s[r0][je]);
                    float2 rp1e = __bfloat1622float2(*(const __nv_bfloat162*)&Rpre_s[r1][je]);
                    float2 rp0o = __bfloat1622float2(*(const __nv_bfloat162*)&Rpre_s[r0][jo]);
                    float2 rp1o = __bfloat1622float2(*(const __nv_bfloat162*)&Rpre_s[r1][jo]);
                    ya0[t] = pack_relu2(acc[2*t][0]   + rp0e.x, acc[2*t][1]   + rp0e.y);
                    ya1[t] = pack_relu2(acc[2*t][2]   + rp1e.x, acc[2*t][3]   + rp1e.y);
                    ya2[t] = pack_relu2(acc[2*t+1][0] + rp0o.x, acc[2*t+1][1] + rp0o.y);
                    ya3[t] = pack_relu2(acc[2*t+1][2] + rp1o.x, acc[2*t+1][3] + rp1o.y);
                }
            }

            // layer 2 (A from registers, B from smem)
            float acc2[8][4];
            #pragma unroll
            for (int nt = 0; nt < 8; nt++)
                #pragma unroll
                for (int q = 0; q < 4; q++) acc2[nt][q] = 0.f;
            #pragma unroll
            for (int t = 0; t < 4; t++) {
                const int kk = 16 * t;
                #pragma unroll
                for (int ntp = 0; ntp < 4; ntp++) {
                    uint32_t bb0, bb1, bb2, bb3;
                    ldm_x4(bb0, bb1, bb2, bb3,
                           baseW2 + ((ntp * 16 + bRowOff) * 72 + kk + bKsel) * 2);
                    mma_bf16(acc2[2 * ntp],     ya0[t], ya1[t], ya2[t], ya3[t], bb0, bb1);
                    mma_bf16(acc2[2 * ntp + 1], ya0[t], ya1[t], ya2[t], ya3[t], bb2, bb3);
                }
            }

            // layer 3 fused
            float p0 = 0.f, p1 = 0.f;
            #pragma unroll
            for (int nt = 0; nt < 8; nt++) {
                int j = nt * 8 + c2;
                p0 += fmaxf(acc2[nt][0] + b2_s[j],     0.f) * w3_s[j];
                p0 += fmaxf(acc2[nt][1] + b2_s[j + 1], 0.f) * w3_s[j + 1];
                p1 += fmaxf(acc2[nt][2] + b2_s[j],     0.f) * w3_s[j];
                p1 += fmaxf(acc2[nt][3] + b2_s[j + 1], 0.f) * w3_s[j + 1];
            }
            p0 += __shfl_xor_sync(0xffffffffu, p0, 1);
            p0 += __shfl_xor_sync(0xffffffffu, p0, 2);
            p1 += __shfl_xor_sync(0xffffffffu, p1, 1);
            p1 += __shfl_xor_sync(0xffffffffu, p1, 2);
            if ((lane & 3) == 0) {
                pi_s[l][m0] = sigmoidf_(p0 + b3v);
                pi_s[l][m1] = sigmoidf_(p1 + b3v);
            }
        }
        __syncthreads();

        // ---- softmax both hops, per warp (pi in [0,1]: no max shift needed) ----
        float w00, w01, w10, w11;
        {
            float e0v = __expf(pi_s[0][lane]), e1v = __expf(pi_s[0][lane + 32]);
            float s = e0v + e1v;
            #pragma unroll
            for (int o = 16; o; o >>= 1) s += __shfl_xor_sync(0xffffffffu, s, o);
            float inv = 1.f / s;
            w00 = e0v * inv; w01 = e1v * inv;
        }
        {
            float e0v = __expf(pi_s[1][lane]), e1v = __expf(pi_s[1][lane + 32]);
            float s = e0v + e1v;
            #pragma unroll
            for (int o = 16; o; o >>= 1) s += __shfl_xor_sync(0xffffffffu, s, o);
            float inv = 1.f / s;
            w10 = e0v * inv; w11 = e1v * inv;
        }

        // ---- gathers: warp quarter = 16 neighbor rows, lane = dim pair ----
        {
            const int mq = wid * 16;
            float2 a0acc = make_float2(0.f, 0.f);
            float2 a1acc = make_float2(0.f, 0.f);
            float2 e0acc = make_float2(0.f, 0.f);
            #pragma unroll
            for (int batch = 0; batch < 2; batch++) {
                float2 v0[8], v1[8], ve[8];
                #pragma unroll
                for (int i = 0; i < 8; i++) {
                    int mm = mq + batch * 8 + i;
                    v0[i] = ((const float2*)(ent_emb + (size_t)tail_s[0][mm] * DIM))[lane];
                    v1[i] = ((const float2*)(ent_emb + (size_t)tail_s[1][mm] * DIM))[lane];
                    ve[i] = ((const float2*)(emb0    + (size_t)e0i_s[mm]     * DIM))[lane];
                }
                #pragma unroll
                for (int i = 0; i < 8; i++) {
                    int mm = mq + batch * 8 + i;
                    float wv0 = (wid < 2) ? __shfl_sync(0xffffffffu, w00, mm)
                                          : __shfl_sync(0xffffffffu, w01, mm - 32);
                    float wv1 = (wid < 2) ? __shfl_sync(0xffffffffu, w10, mm)
                                          : __shfl_sync(0xffffffffu, w11, mm - 32);
                    a0acc.x = fmaf(wv0, v0[i].x, a0acc.x);
                    a0acc.y = fmaf(wv0, v0[i].y, a0acc.y);
                    a1acc.x = fmaf(wv1, v1[i].x, a1acc.x);
                    a1acc.y = fmaf(wv1, v1[i].y, a1acc.y);
                    e0acc.x += ve[i].x;
                    e0acc.y += ve[i].y;
                }
            }
            ap4[0][wid][lane] = a0acc;
            ap4[1][wid][lane] = a1acc;
            e0p4[wid][lane]   = e0acc;
        }
        __syncthreads();

        // ---- build emb[192] ----
        if (tid < 96) {
            int seg = tid >> 5, p = tid & 31;
            float2 s = make_float2(0.f, 0.f);
            #pragma unroll
            for (int w = 0; w < 4; w++) {
                float2 v = (seg == 0) ? e0p4[w][p] : ap4[seg - 1][w][p];
                s.x += v.x; s.y += v.y;
            }
            if (seg == 0) { s.x *= (1.f / 64.f); s.y *= (1.f / 64.f); }
            ((float2*)emb_s)[tid] = s;
        }
        __syncthreads();

        // ---- agg GEMV ----
        {
            float acc = 0.f;
            const __nv_bfloat16* wt = g_waggTb + (size_t)(h2 * 96) * DIM + dd;
            #pragma unroll 12
            for (int k = 0; k < 96; k++)
                acc = fmaf(emb_s[h2 * 96 + k], __bfloat162float(wt[(size_t)k * DIM]), acc);
            aggp_s[h2][dd] = acc;
        }
        __syncthreads();
        if (tid < 64)
            g_side[side][b][tid] = sigmoidf_(aggp_s[0][tid] + aggp_s[1][tid] + bagg_s[tid]);
        __syncthreads();   // everyone done with smem + next_s consumed next at top
    }
}

// ---------------------------------------------------------------------------
// Combine: out[b] = sigmoid(users[b] · items[b]); one warp per b.
// ---------------------------------------------------------------------------
__global__ void combine_kernel(float* __restrict__ out) {
    int gw   = (blockIdx.x * blockDim.x + threadIdx.x) >> 5;
    int lane = threadIdx.x & 31;
    if (gw >= NB) return;
    float s = g_side[0][gw][lane]      * g_side[1][gw][lane]
            + g_side[0][gw][lane + 32] * g_side[1][gw][lane + 32];
    #pragma unroll
    for (int o = 16; o; o >>= 1) s += __shfl_down_sync(0xffffffffu, s, o);
    if (lane == 0) out[gw] = sigmoidf_(s);
}

extern "C" void kernel_launch(void* const* d_in, const int* in_sizes, int n_in,
                              void* d_out, int out_size) {
    const float* ent_emb = (const float*)d_in[0];
    const float* rec_emb = (const float*)d_in[1];
    const float* rel_emb = (const float*)d_in[2];
    const float* w1      = (const float*)d_in[3];
    const float* b1      = (const float*)d_in[4];
    const float* w2      = (const float*)d_in[5];
    const float* b2      = (const float*)d_in[6];
    const float* w3      = (const float*)d_in[7];
    const float* b3      = (const float*)d_in[8];
    const float* wagg    = (const float*)d_in[9];
    const float* bagg    = (const float*)d_in[10];
    const int*   u_ent   = (const int*)d_in[11];
    const int*   u_heads = (const int*)d_in[12];
    const int*   u_rels  = (const int*)d_in[13];
    const int*   u_tails = (const int*)d_in[14];
    const int*   v_ent   = (const int*)d_in[15];
    const int*   v_heads = (const int*)d_in[16];
    const int*   v_rels  = (const int*)d_in[17];
    const int*   v_tails = (const int*)d_in[18];

    prep_kernel<<<56, 128>>>(rel_emb, w1, b1, w2, wagg);
    attn_kernel<<<GRIDP, 128>>>(ent_emb, rec_emb, b2, w3, b3, bagg,
                                u_ent, u_heads, u_rels, u_tails,
                                v_ent, v_heads, v_rels, v_tails);
    combine_kernel<<<NB / 8, 256>>>((float*)d_out);
}